// round 5
// baseline (speedup 1.0000x reference)
#include <cuda_runtime.h>
#include <cuda_bf16.h>
#include <cstdint>

// B=4, N=4096, D=256
// scores = (V V^T)/16 ; edges = softsign(scores)
// dstate = edges @ state ; dval = edges @ val
// Split-bf16 (hi/lo, 3-term) HMMA flash kernel; cp.async double-buffered,
// term-major mma scheduling (no accumulator RAW chains).

#define BATCH 4
#define NN 4096
#define DD 256
#define BM 128
#define BJH 32            // half j-tile (pipeline stage)
#define NHALF (NN / BJH)  // 128
#define THREADS 256
#define ROWB 528          // 33 x 16B per 256-bf16 row (conflict-free padding)

static constexpr uint32_t S_VIH = 0;
static constexpr uint32_t S_VIL = 128u * ROWB;
static constexpr uint32_t S_VJ0 = 2u * 128u * ROWB;
static constexpr uint32_t S_VJ1 = S_VJ0 + 64u * ROWB;
static constexpr uint32_t VJ_LO = 32u * ROWB;
static constexpr uint32_t S_ST0 = S_VJ1 + 64u * ROWB;
static constexpr uint32_t S_ST1 = S_ST0 + 128u;
static constexpr uint32_t SMEM_BYTES = S_ST1 + 128u;

__device__ __nv_bfloat16 g_vhi[(size_t)BATCH * NN * DD];
__device__ __nv_bfloat16 g_vlo[(size_t)BATCH * NN * DD];

__device__ __forceinline__ uint32_t smem_u32(const void* p) {
    uint32_t a;
    asm("{ .reg .u64 t; cvta.to.shared.u64 t, %1; cvt.u32.u64 %0, t; }" : "=r"(a) : "l"(p));
    return a;
}
__device__ __forceinline__ void cpa16(uint32_t dst, const void* src) {
    asm volatile("cp.async.cg.shared.global [%0], [%1], 16;" :: "r"(dst), "l"(src) : "memory");
}
#define CP_COMMIT() asm volatile("cp.async.commit_group;" ::: "memory")
#define CP_WAIT1()  asm volatile("cp.async.wait_group 1;" ::: "memory")

__device__ __forceinline__ void ldm_x4(uint32_t* r, uint32_t addr) {
    asm volatile("ldmatrix.sync.aligned.m8n8.x4.shared.b16 {%0,%1,%2,%3}, [%4];"
        : "=r"(r[0]), "=r"(r[1]), "=r"(r[2]), "=r"(r[3]) : "r"(addr));
}
__device__ __forceinline__ void ldm_x4_t(uint32_t* r, uint32_t addr) {
    asm volatile("ldmatrix.sync.aligned.m8n8.x4.trans.shared.b16 {%0,%1,%2,%3}, [%4];"
        : "=r"(r[0]), "=r"(r[1]), "=r"(r[2]), "=r"(r[3]) : "r"(addr));
}
__device__ __forceinline__ void mma16816(float* c, const uint32_t* a, const uint32_t* b) {
    asm volatile("mma.sync.aligned.m16n8k16.row.col.f32.bf16.bf16.f32 "
        "{%0,%1,%2,%3}, {%4,%5,%6,%7}, {%8,%9}, {%0,%1,%2,%3};"
        : "+f"(c[0]), "+f"(c[1]), "+f"(c[2]), "+f"(c[3])
        : "r"(a[0]), "r"(a[1]), "r"(a[2]), "r"(a[3]), "r"(b[0]), "r"(b[1]));
}
__device__ __forceinline__ uint32_t hi2(float x, float y) {
    return __byte_perm(__float_as_uint(x), __float_as_uint(y), 0x7632);
}
__device__ __forceinline__ uint32_t lo2(float x, float y) {
    float hx = __uint_as_float(__float_as_uint(x) & 0xFFFF0000u);
    float hy = __uint_as_float(__float_as_uint(y) & 0xFFFF0000u);
    __nv_bfloat162 t = __floats2bfloat162_rn(x - hx, y - hy);
    return *reinterpret_cast<uint32_t*>(&t);
}

__global__ __launch_bounds__(256) void split_kernel(const float* __restrict__ val) {
    const int b = blockIdx.y, n0 = blockIdx.x * 64;
    const size_t base = ((size_t)b * NN + n0) * DD;
    #pragma unroll
    for (int k = 0; k < 16; k++) {
        int u = threadIdx.x + 256 * k;
        float4 v = *(const float4*)(val + base + (size_t)u * 4);
        *(uint2*)(g_vhi + base + (size_t)u * 4) = make_uint2(hi2(v.x, v.y), hi2(v.z, v.w));
        *(uint2*)(g_vlo + base + (size_t)u * 4) = make_uint2(lo2(v.x, v.y), lo2(v.z, v.w));
    }
}

__global__ __launch_bounds__(THREADS, 1)
void prop_hmma(const float* __restrict__ state,
               float* __restrict__ dstate, float* __restrict__ dval)
{
    extern __shared__ char smem[];
    const uint32_t sb = smem_u32(smem);
    const int tid = threadIdx.x, l = tid & 31, wid = tid >> 5;
    const int b = blockIdx.y, i0 = blockIdx.x * BM;
    const int mrow = wid * 16;
    const size_t vbase = (size_t)b * NN * DD;

    // ---- prologue fill: Vi + j-half 0 ----
    {
        #pragma unroll
        for (int k = 0; k < 32; k++) {
            int u = tid + 256 * k;
            int row = u >> 6, rem = u & 63;
            int half = rem >> 5, ch = rem & 31;
            uint32_t dst = sb + (half ? S_VIL : S_VIH) + (uint32_t)(row * ROWB + ch * 16);
            const __nv_bfloat16* src = (half ? g_vlo : g_vhi) + vbase + (size_t)(i0 + row) * DD + ch * 8;
            cpa16(dst, src);
        }
        #pragma unroll
        for (int k = 0; k < 8; k++) {
            int u = tid + 256 * k;
            int row = u >> 6, rem = u & 63;
            int half = rem >> 5, ch = rem & 31;
            uint32_t dst = sb + S_VJ0 + (half ? VJ_LO : 0u) + (uint32_t)(row * ROWB + ch * 16);
            const __nv_bfloat16* src = (half ? g_vlo : g_vhi) + vbase + (size_t)row * DD + ch * 8;
            cpa16(dst, src);
        }
        if (tid < 8) cpa16(sb + S_ST0 + tid * 16, state + (size_t)b * NN + tid * 4);
        CP_COMMIT();
    }

    const uint32_t offA  = (uint32_t)((l & 15) * ROWB + (l >> 4) * 16);
    const uint32_t offBn = (uint32_t)(((l & 7) + ((l & 16) ? 8 : 0)) * ROWB + ((l >> 3) & 1) * 16);
    const uint32_t viH = sb + S_VIH + mrow * ROWB + offA;
    const uint32_t viL = sb + S_VIL + mrow * ROWB + offA;

    float dacc[32][4];
    #pragma unroll
    for (int t = 0; t < 32; t++) { dacc[t][0] = dacc[t][1] = dacc[t][2] = dacc[t][3] = 0.f; }
    float ds0 = 0.f, ds1 = 0.f;
    const float scale = 0.0625f;
    const int c0 = 2 * (l & 3);

    for (int h = 0; h < NHALF; h++) {
        // ---- issue fill(h+1) ----
        {
            int hn = h + 1;
            if (hn < NHALF) {
                const int j0 = hn * BJH;
                uint32_t bufb = sb + ((hn & 1) ? S_VJ1 : S_VJ0);
                #pragma unroll
                for (int k = 0; k < 8; k++) {
                    int u = tid + 256 * k;
                    int row = u >> 6, rem = u & 63;
                    int half = rem >> 5, ch = rem & 31;
                    uint32_t dst = bufb + (half ? VJ_LO : 0u) + (uint32_t)(row * ROWB + ch * 16);
                    const __nv_bfloat16* src = (half ? g_vlo : g_vhi) + vbase + (size_t)(j0 + row) * DD + ch * 8;
                    cpa16(dst, src);
                }
                if (tid < 8)
                    cpa16(sb + ((hn & 1) ? S_ST1 : S_ST0) + tid * 16,
                          state + (size_t)b * NN + j0 + tid * 4);
            }
            CP_COMMIT();
        }
        CP_WAIT1();
        __syncthreads();

        const uint32_t bufb = sb + ((h & 1) ? S_VJ1 : S_VJ0);
        const uint32_t vjB = bufb + offBn;
        const uint32_t vjT = bufb + offA;
        const float* stp = (const float*)(smem + ((h & 1) ? S_ST1 : S_ST0));

        // ---- Phase A: term-major, reuse distance 4 ----
        float sacc[4][4];
        #pragma unroll
        for (int t = 0; t < 4; t++) { sacc[t][0] = sacc[t][1] = sacc[t][2] = sacc[t][3] = 0.f; }

        #pragma unroll
        for (int s = 0; s < 16; s++) {
            uint32_t ah[4], al[4], bh0[4], bh1[4], bl0[4], bl1[4];
            ldm_x4(ah, viH + s * 32);
            ldm_x4(al, viL + s * 32);
            ldm_x4(bh0, vjB + s * 32);
            ldm_x4(bh1, vjB + 16 * ROWB + s * 32);
            ldm_x4(bl0, vjB + VJ_LO + s * 32);
            ldm_x4(bl1, vjB + VJ_LO + 16 * ROWB + s * 32);
            // hh
            mma16816(sacc[0], ah, bh0 + 0);
            mma16816(sacc[1], ah, bh0 + 2);
            mma16816(sacc[2], ah, bh1 + 0);
            mma16816(sacc[3], ah, bh1 + 2);
            // hl
            mma16816(sacc[0], ah, bl0 + 0);
            mma16816(sacc[1], ah, bl0 + 2);
            mma16816(sacc[2], ah, bl1 + 0);
            mma16816(sacc[3], ah, bl1 + 2);
            // lh
            mma16816(sacc[0], al, bh0 + 0);
            mma16816(sacc[1], al, bh0 + 2);
            mma16816(sacc[2], al, bh1 + 0);
            mma16816(sacc[3], al, bh1 + 2);
        }

        // ---- epilogue ----
        uint32_t eh[2][4], el[2][4];
        #pragma unroll
        for (int t = 0; t < 4; t++) {
            float f0 = sacc[t][0] * scale, f1 = sacc[t][1] * scale;
            float f2 = sacc[t][2] * scale, f3 = sacc[t][3] * scale;
            float e0 = __fdividef(f0, 1.0f + fabsf(f0));
            float e1 = __fdividef(f1, 1.0f + fabsf(f1));
            float e2 = __fdividef(f2, 1.0f + fabsf(f2));
            float e3 = __fdividef(f3, 1.0f + fabsf(f3));
            float sA = stp[8 * t + c0], sB = stp[8 * t + c0 + 1];
            ds0 += e0 * sA + e1 * sB;
            ds1 += e2 * sA + e3 * sB;
            int kt = t >> 1, hh = (t & 1) * 2;
            eh[kt][hh]     = hi2(e0, e1);
            eh[kt][hh + 1] = hi2(e2, e3);
            el[kt][hh]     = lo2(e0, e1);
            el[kt][hh + 1] = lo2(e2, e3);
        }

        // ---- Phase B: blocks of 4 n-tiles, term-major (reuse distance 8) ----
        #pragma unroll
        for (int kt = 0; kt < 2; kt++) {
            uint32_t tb = vjT + kt * (16 * ROWB);
            #pragma unroll
            for (int blk = 0; blk < 4; blk++) {
                uint32_t bh[4][4], bl[4][4];
                #pragma unroll
                for (int j = 0; j < 4; j++) {
                    int nt2 = blk * 4 + j;
                    ldm_x4_t(bh[j], tb + nt2 * 32);
                    ldm_x4_t(bl[j], tb + VJ_LO + nt2 * 32);
                }
                #pragma unroll
                for (int j = 0; j < 4; j++) {           // hh
                    int nt2 = blk * 4 + j;
                    mma16816(dacc[2 * nt2],     eh[kt], bh[j] + 0);
                    mma16816(dacc[2 * nt2 + 1], eh[kt], bh[j] + 2);
                }
                #pragma unroll
                for (int j = 0; j < 4; j++) {           // hl
                    int nt2 = blk * 4 + j;
                    mma16816(dacc[2 * nt2],     eh[kt], bl[j] + 0);
                    mma16816(dacc[2 * nt2 + 1], eh[kt], bl[j] + 2);
                }
                #pragma unroll
                for (int j = 0; j < 4; j++) {           // lh
                    int nt2 = blk * 4 + j;
                    mma16816(dacc[2 * nt2],     el[kt], bh[j] + 0);
                    mma16816(dacc[2 * nt2 + 1], el[kt], bh[j] + 2);
                }
            }
        }
        __syncthreads();
    }

    // ---- write dval ----
    {
        const int row = i0 + mrow + (l >> 2);
        float* d0 = dval + (size_t)b * NN * DD + (size_t)row * DD;
        float* d1 = d0 + 8 * DD;
        #pragma unroll
        for (int nt = 0; nt < 32; nt++) {
            int c = 8 * nt + c0;
            *(float2*)(d0 + c) = make_float2(dacc[nt][0], dacc[nt][1]);
            *(float2*)(d1 + c) = make_float2(dacc[nt][2], dacc[nt][3]);
        }
    }
    // ---- dstate ----
    ds0 += __shfl_xor_sync(0xFFFFFFFFu, ds0, 1);
    ds0 += __shfl_xor_sync(0xFFFFFFFFu, ds0, 2);
    ds1 += __shfl_xor_sync(0xFFFFFFFFu, ds1, 1);
    ds1 += __shfl_xor_sync(0xFFFFFFFFu, ds1, 2);
    if ((l & 3) == 0) {
        int r = i0 + mrow + (l >> 2);
        dstate[(size_t)b * NN + r]     = ds0;
        dstate[(size_t)b * NN + r + 8] = ds1;
    }
}

extern "C" void kernel_launch(void* const* d_in, const int* in_sizes, int n_in,
                              void* d_out, int out_size)
{
    const float* val   = (const float*)d_in[0];   // [B, N, D]
    const float* state = (const float*)d_in[1];   // [B, N]
    float* dstate = (float*)d_out;                // [B, N]
    float* dval   = dstate + (size_t)BATCH * NN;  // [B, N, D]
    (void)in_sizes; (void)n_in; (void)out_size;

    dim3 gs(NN / 64, BATCH);
    split_kernel<<<gs, 256>>>(val);

    cudaFuncSetAttribute(prop_hmma,
                         cudaFuncAttributeMaxDynamicSharedMemorySize, (int)SMEM_BYTES);
    dim3 grid(NN / BM, BATCH);
    prop_hmma<<<grid, THREADS, SMEM_BYTES>>>(state, dstate, dval);
}

// round 6
// speedup vs baseline: 1.1943x; 1.1943x over previous
#include <cuda_runtime.h>
#include <cuda_fp16.h>
#include <cstdint>

// B=4, N=4096, D=256
// scores = (V V^T)/16 ; edges = softsign(scores)
// dstate = edges @ state ; dval = edges @ val
// fp16 split pipeline: phase A 3-term (hi/lo), phase B 2-term (E fp16 single,
// V hi/lo). cp.async double-buffered, term-major mma scheduling.

#define BATCH 4
#define NN 4096
#define DD 256
#define BM 128
#define BJH 32            // half j-tile (pipeline stage)
#define NHALF (NN / BJH)  // 128
#define THREADS 256
#define ROWB 528          // 33 x 16B per 256-elem fp16 row (conflict-free padding)

static constexpr uint32_t S_VIH = 0;
static constexpr uint32_t S_VIL = 128u * ROWB;
static constexpr uint32_t S_VJ0 = 2u * 128u * ROWB;
static constexpr uint32_t S_VJ1 = S_VJ0 + 64u * ROWB;
static constexpr uint32_t VJ_LO = 32u * ROWB;
static constexpr uint32_t S_ST0 = S_VJ1 + 64u * ROWB;
static constexpr uint32_t S_ST1 = S_ST0 + 128u;
static constexpr uint32_t SMEM_BYTES = S_ST1 + 128u;

__device__ __half g_vhi[(size_t)BATCH * NN * DD];
__device__ __half g_vlo[(size_t)BATCH * NN * DD];

__device__ __forceinline__ uint32_t smem_u32(const void* p) {
    uint32_t a;
    asm("{ .reg .u64 t; cvta.to.shared.u64 t, %1; cvt.u32.u64 %0, t; }" : "=r"(a) : "l"(p));
    return a;
}
__device__ __forceinline__ void cpa16(uint32_t dst, const void* src) {
    asm volatile("cp.async.cg.shared.global [%0], [%1], 16;" :: "r"(dst), "l"(src) : "memory");
}
#define CP_COMMIT() asm volatile("cp.async.commit_group;" ::: "memory")
#define CP_WAIT1()  asm volatile("cp.async.wait_group 1;" ::: "memory")

__device__ __forceinline__ void ldm_x4(uint32_t* r, uint32_t addr) {
    asm volatile("ldmatrix.sync.aligned.m8n8.x4.shared.b16 {%0,%1,%2,%3}, [%4];"
        : "=r"(r[0]), "=r"(r[1]), "=r"(r[2]), "=r"(r[3]) : "r"(addr));
}
__device__ __forceinline__ void ldm_x4_t(uint32_t* r, uint32_t addr) {
    asm volatile("ldmatrix.sync.aligned.m8n8.x4.trans.shared.b16 {%0,%1,%2,%3}, [%4];"
        : "=r"(r[0]), "=r"(r[1]), "=r"(r[2]), "=r"(r[3]) : "r"(addr));
}
__device__ __forceinline__ void mma16816(float* c, const uint32_t* a, const uint32_t* b) {
    asm volatile("mma.sync.aligned.m16n8k16.row.col.f32.f16.f16.f32 "
        "{%0,%1,%2,%3}, {%4,%5,%6,%7}, {%8,%9}, {%0,%1,%2,%3};"
        : "+f"(c[0]), "+f"(c[1]), "+f"(c[2]), "+f"(c[3])
        : "r"(a[0]), "r"(a[1]), "r"(a[2]), "r"(a[3]), "r"(b[0]), "r"(b[1]));
}
// pack two floats -> two fp16 (rn)
__device__ __forceinline__ uint32_t h2pk(float x, float y) {
    __half2 t = __floats2half2_rn(x, y);
    return *reinterpret_cast<uint32_t*>(&t);
}
// residual after fp16 rn
__device__ __forceinline__ uint32_t h2lo(float x, float y) {
    float hx = __half2float(__float2half_rn(x));
    float hy = __half2float(__float2half_rn(y));
    __half2 t = __floats2half2_rn(x - hx, y - hy);
    return *reinterpret_cast<uint32_t*>(&t);
}

__global__ __launch_bounds__(256) void split_kernel(const float* __restrict__ val) {
    const int b = blockIdx.y, n0 = blockIdx.x * 64;
    const size_t base = ((size_t)b * NN + n0) * DD;
    #pragma unroll
    for (int k = 0; k < 16; k++) {
        int u = threadIdx.x + 256 * k;
        float4 v = *(const float4*)(val + base + (size_t)u * 4);
        *(uint2*)(g_vhi + base + (size_t)u * 4) = make_uint2(h2pk(v.x, v.y), h2pk(v.z, v.w));
        *(uint2*)(g_vlo + base + (size_t)u * 4) = make_uint2(h2lo(v.x, v.y), h2lo(v.z, v.w));
    }
}

__global__ __launch_bounds__(THREADS, 1)
void prop_hmma(const float* __restrict__ state,
               float* __restrict__ dstate, float* __restrict__ dval)
{
    extern __shared__ char smem[];
    const uint32_t sb = smem_u32(smem);
    const int tid = threadIdx.x, l = tid & 31, wid = tid >> 5;
    const int b = blockIdx.y, i0 = blockIdx.x * BM;
    const int mrow = wid * 16;
    const size_t vbase = (size_t)b * NN * DD;

    // ---- prologue fill: Vi + j-half 0 ----
    {
        #pragma unroll
        for (int k = 0; k < 32; k++) {
            int u = tid + 256 * k;
            int row = u >> 6, rem = u & 63;
            int half = rem >> 5, ch = rem & 31;
            uint32_t dst = sb + (half ? S_VIL : S_VIH) + (uint32_t)(row * ROWB + ch * 16);
            const __half* src = (half ? g_vlo : g_vhi) + vbase + (size_t)(i0 + row) * DD + ch * 8;
            cpa16(dst, src);
        }
        #pragma unroll
        for (int k = 0; k < 8; k++) {
            int u = tid + 256 * k;
            int row = u >> 6, rem = u & 63;
            int half = rem >> 5, ch = rem & 31;
            uint32_t dst = sb + S_VJ0 + (half ? VJ_LO : 0u) + (uint32_t)(row * ROWB + ch * 16);
            const __half* src = (half ? g_vlo : g_vhi) + vbase + (size_t)row * DD + ch * 8;
            cpa16(dst, src);
        }
        if (tid < 8) cpa16(sb + S_ST0 + tid * 16, state + (size_t)b * NN + tid * 4);
        CP_COMMIT();
    }

    const uint32_t offA  = (uint32_t)((l & 15) * ROWB + (l >> 4) * 16);
    const uint32_t offBn = (uint32_t)(((l & 7) + ((l & 16) ? 8 : 0)) * ROWB + ((l >> 3) & 1) * 16);
    const uint32_t viH = sb + S_VIH + mrow * ROWB + offA;
    const uint32_t viL = sb + S_VIL + mrow * ROWB + offA;

    float dacc[32][4];
    #pragma unroll
    for (int t = 0; t < 32; t++) { dacc[t][0] = dacc[t][1] = dacc[t][2] = dacc[t][3] = 0.f; }
    float ds0 = 0.f, ds1 = 0.f;
    const float scale = 0.0625f;
    const int c0 = 2 * (l & 3);

    for (int h = 0; h < NHALF; h++) {
        // ---- issue fill(h+1) ----
        {
            int hn = h + 1;
            if (hn < NHALF) {
                const int j0 = hn * BJH;
                uint32_t bufb = sb + ((hn & 1) ? S_VJ1 : S_VJ0);
                #pragma unroll
                for (int k = 0; k < 8; k++) {
                    int u = tid + 256 * k;
                    int row = u >> 6, rem = u & 63;
                    int half = rem >> 5, ch = rem & 31;
                    uint32_t dst = bufb + (half ? VJ_LO : 0u) + (uint32_t)(row * ROWB + ch * 16);
                    const __half* src = (half ? g_vlo : g_vhi) + vbase + (size_t)(j0 + row) * DD + ch * 8;
                    cpa16(dst, src);
                }
                if (tid < 8)
                    cpa16(sb + ((hn & 1) ? S_ST1 : S_ST0) + tid * 16,
                          state + (size_t)b * NN + j0 + tid * 4);
            }
            CP_COMMIT();
        }
        CP_WAIT1();
        __syncthreads();

        const uint32_t bufb = sb + ((h & 1) ? S_VJ1 : S_VJ0);
        const uint32_t vjB = bufb + offBn;
        const uint32_t vjT = bufb + offA;
        const float* stp = (const float*)(smem + ((h & 1) ? S_ST1 : S_ST0));

        // ---- Phase A: 3-term fp16, term-major ----
        float sacc[4][4];
        #pragma unroll
        for (int t = 0; t < 4; t++) { sacc[t][0] = sacc[t][1] = sacc[t][2] = sacc[t][3] = 0.f; }

        #pragma unroll
        for (int s = 0; s < 16; s++) {
            uint32_t ah[4], al[4], bh0[4], bh1[4], bl0[4], bl1[4];
            ldm_x4(ah, viH + s * 32);
            ldm_x4(al, viL + s * 32);
            ldm_x4(bh0, vjB + s * 32);
            ldm_x4(bh1, vjB + 16 * ROWB + s * 32);
            ldm_x4(bl0, vjB + VJ_LO + s * 32);
            ldm_x4(bl1, vjB + VJ_LO + 16 * ROWB + s * 32);
            mma16816(sacc[0], ah, bh0 + 0);
            mma16816(sacc[1], ah, bh0 + 2);
            mma16816(sacc[2], ah, bh1 + 0);
            mma16816(sacc[3], ah, bh1 + 2);
            mma16816(sacc[0], ah, bl0 + 0);
            mma16816(sacc[1], ah, bl0 + 2);
            mma16816(sacc[2], ah, bl1 + 0);
            mma16816(sacc[3], ah, bl1 + 2);
            mma16816(sacc[0], al, bh0 + 0);
            mma16816(sacc[1], al, bh0 + 2);
            mma16816(sacc[2], al, bh1 + 0);
            mma16816(sacc[3], al, bh1 + 2);
        }

        // ---- epilogue: softsign (fp32), dstate partial, E -> fp16 a-frags ----
        uint32_t eh[2][4];
        #pragma unroll
        for (int t = 0; t < 4; t++) {
            float f0 = sacc[t][0] * scale, f1 = sacc[t][1] * scale;
            float f2 = sacc[t][2] * scale, f3 = sacc[t][3] * scale;
            float e0 = __fdividef(f0, 1.0f + fabsf(f0));
            float e1 = __fdividef(f1, 1.0f + fabsf(f1));
            float e2 = __fdividef(f2, 1.0f + fabsf(f2));
            float e3 = __fdividef(f3, 1.0f + fabsf(f3));
            float sA = stp[8 * t + c0], sB = stp[8 * t + c0 + 1];
            ds0 += e0 * sA + e1 * sB;
            ds1 += e2 * sA + e3 * sB;
            int kt = t >> 1, hh = (t & 1) * 2;
            eh[kt][hh]     = h2pk(e0, e1);
            eh[kt][hh + 1] = h2pk(e2, e3);
        }

        // ---- Phase B: 2-term (E fp16 x {Vh, Vl}), blocks of 4, term-major ----
        #pragma unroll
        for (int kt = 0; kt < 2; kt++) {
            uint32_t tb = vjT + kt * (16 * ROWB);
            #pragma unroll
            for (int blk = 0; blk < 4; blk++) {
                uint32_t bh[4][4], bl[4][4];
                #pragma unroll
                for (int j = 0; j < 4; j++) {
                    int nt2 = blk * 4 + j;
                    ldm_x4_t(bh[j], tb + nt2 * 32);
                    ldm_x4_t(bl[j], tb + VJ_LO + nt2 * 32);
                }
                #pragma unroll
                for (int j = 0; j < 4; j++) {           // E * Vhi
                    int nt2 = blk * 4 + j;
                    mma16816(dacc[2 * nt2],     eh[kt], bh[j] + 0);
                    mma16816(dacc[2 * nt2 + 1], eh[kt], bh[j] + 2);
                }
                #pragma unroll
                for (int j = 0; j < 4; j++) {           // E * Vlo
                    int nt2 = blk * 4 + j;
                    mma16816(dacc[2 * nt2],     eh[kt], bl[j] + 0);
                    mma16816(dacc[2 * nt2 + 1], eh[kt], bl[j] + 2);
                }
            }
        }
        __syncthreads();
    }

    // ---- write dval ----
    {
        const int row = i0 + mrow + (l >> 2);
        float* d0 = dval + (size_t)b * NN * DD + (size_t)row * DD;
        float* d1 = d0 + 8 * DD;
        #pragma unroll
        for (int nt = 0; nt < 32; nt++) {
            int c = 8 * nt + c0;
            *(float2*)(d0 + c) = make_float2(dacc[nt][0], dacc[nt][1]);
            *(float2*)(d1 + c) = make_float2(dacc[nt][2], dacc[nt][3]);
        }
    }
    // ---- dstate ----
    ds0 += __shfl_xor_sync(0xFFFFFFFFu, ds0, 1);
    ds0 += __shfl_xor_sync(0xFFFFFFFFu, ds0, 2);
    ds1 += __shfl_xor_sync(0xFFFFFFFFu, ds1, 1);
    ds1 += __shfl_xor_sync(0xFFFFFFFFu, ds1, 2);
    if ((l & 3) == 0) {
        int r = i0 + mrow + (l >> 2);
        dstate[(size_t)b * NN + r]     = ds0;
        dstate[(size_t)b * NN + r + 8] = ds1;
    }
}

extern "C" void kernel_launch(void* const* d_in, const int* in_sizes, int n_in,
                              void* d_out, int out_size)
{
    const float* val   = (const float*)d_in[0];   // [B, N, D]
    const float* state = (const float*)d_in[1];   // [B, N]
    float* dstate = (float*)d_out;                // [B, N]
    float* dval   = dstate + (size_t)BATCH * NN;  // [B, N, D]
    (void)in_sizes; (void)n_in; (void)out_size;

    dim3 gs(NN / 64, BATCH);
    split_kernel<<<gs, 256>>>(val);

    cudaFuncSetAttribute(prop_hmma,
                         cudaFuncAttributeMaxDynamicSharedMemorySize, (int)SMEM_BYTES);
    dim3 grid(NN / BM, BATCH);
    prop_hmma<<<grid, THREADS, SMEM_BYTES>>>(state, dstate, dval);
}